// round 12
// baseline (speedup 1.0000x reference)
#include <cuda_runtime.h>
#include <cuda_fp16.h>
#include <cstdint>

#define MAXN 40000
#define MAXE 1048576
#define FDIM 128
#define SCAN_BLK 1024
#define MAX_PART 64
#define XPITCH 68     // words, X tile pitch (bank-distinct A frags)
#define WPITCH16 136  // words, W tile pitch (bank-distinct B frags)

// Static scratch (no allocation allowed)
__device__ unsigned long long g_pack[MAXN];  // deg<<40 | sumw*2^20
__device__ float g_scales [2 * MAXN];        // [0,N): sm   [N,2N): sh
__device__ int   g_off    [MAXN + 1];
__device__ int   g_cursor [MAXN];
__device__ int   g_part   [MAX_PART];
__device__ int   g_partoff[MAX_PART];
__device__ int2  g_epack  [MAXE];            // .x = src, .y = float bits of w
__device__ uint2 g_Xf [MAXN * (FDIM / 4)];   // X in fp16 (half2 pairs)
__device__ float g_h1 [MAXN * FDIM];
__device__ float g_h2 [MAXN * FDIM];

// ---------------------------------------------------------------------------
// 4 edges per thread, int4/float4 streams, 4 independent atomics (MLP=4)
__global__ void edge_stats_kernel(const int4* __restrict__ dst4,
                                  const float4* __restrict__ w4, int nq) {
    int i = blockIdx.x * blockDim.x + threadIdx.x;
    if (i >= nq) return;
    int4 d = dst4[i];
    float4 w = w4[i];
    atomicAdd(&g_pack[d.x], (1ULL << 40) | (unsigned long long)__float2uint_rn(w.x * 1048576.f));
    atomicAdd(&g_pack[d.y], (1ULL << 40) | (unsigned long long)__float2uint_rn(w.y * 1048576.f));
    atomicAdd(&g_pack[d.z], (1ULL << 40) | (unsigned long long)__float2uint_rn(w.z * 1048576.f));
    atomicAdd(&g_pack[d.w], (1ULL << 40) | (unsigned long long)__float2uint_rn(w.w * 1048576.f));
}

// tail edges (E not multiple of 4)
__global__ void edge_stats_tail_kernel(const int* __restrict__ dst,
                                       const float* __restrict__ w,
                                       int start, int E) {
    int e = start + blockIdx.x * blockDim.x + threadIdx.x;
    if (e >= E) return;
    atomicAdd(&g_pack[dst[e]],
              (1ULL << 40) | (unsigned long long)__float2uint_rn(w[e] * 1048576.f));
}

__global__ void __launch_bounds__(SCAN_BLK)
scan_partial_kernel(int n) {
    __shared__ int sh[SCAN_BLK];
    int tid = threadIdx.x;
    int i = blockIdx.x * SCAN_BLK + tid;
    sh[tid] = (i < n) ? (int)(g_pack[i] >> 40) : 0;
    __syncthreads();
    for (int d = SCAN_BLK / 2; d > 0; d >>= 1) {
        if (tid < d) sh[tid] += sh[tid + d];
        __syncthreads();
    }
    if (tid == 0) g_part[blockIdx.x] = sh[0];
}

__global__ void scan_top_kernel(int nb, int n) {
    __shared__ int sh[MAX_PART];
    int tid = threadIdx.x;
    int v = (tid < nb) ? g_part[tid] : 0;
    sh[tid] = v;
    __syncthreads();
    for (int d = 1; d < MAX_PART; d <<= 1) {
        int t = (tid >= d) ? sh[tid - d] : 0;
        __syncthreads();
        sh[tid] += t;
        __syncthreads();
    }
    if (tid < nb) g_partoff[tid] = sh[tid] - v;
    if (tid == 0) g_off[n] = sh[nb - 1];
}

__global__ void __launch_bounds__(SCAN_BLK)
scan_emit_kernel(int n) {
    __shared__ int sh[SCAN_BLK];
    int tid = threadIdx.x;
    int i = blockIdx.x * SCAN_BLK + tid;
    unsigned long long pk = (i < n) ? g_pack[i] : 0ULL;
    int dg = (int)(pk >> 40);
    sh[tid] = dg;
    __syncthreads();
    for (int d = 1; d < SCAN_BLK; d <<= 1) {
        int t = (tid >= d) ? sh[tid - d] : 0;
        __syncthreads();
        sh[tid] += t;
        __syncthreads();
    }
    if (i < n) {
        int ex = sh[tid] - dg + g_partoff[blockIdx.x];
        g_off[i]    = ex;
        g_cursor[i] = ex;
        float sw = (float)(pk & ((1ULL << 40) - 1ULL)) * (1.0f / 1048576.f);
        float dgf = (float)dg;
        float smv = 0.f, shv = 0.f;
        if (dg > 0) {
            float inv = 1.0f / (dgf + 1.0f);
            shv = inv;
            float swp = (sw == 0.f) ? 1.f : sw;
            smv = dgf * inv / swp;
        }
        g_scales[i]     = smv;
        g_scales[n + i] = shv;
    }
}

// 4 edges per thread (MLP=4 on cursor atomics)
__global__ void scatter_kernel(const int4* __restrict__ src4,
                               const int4* __restrict__ dst4,
                               const float4* __restrict__ w4, int nq) {
    int i = blockIdx.x * blockDim.x + threadIdx.x;
    if (i >= nq) return;
    int4 s = src4[i];
    int4 d = dst4[i];
    float4 w = w4[i];
    int p0 = atomicAdd(&g_cursor[d.x], 1);
    int p1 = atomicAdd(&g_cursor[d.y], 1);
    int p2 = atomicAdd(&g_cursor[d.z], 1);
    int p3 = atomicAdd(&g_cursor[d.w], 1);
    g_epack[p0] = make_int2(s.x, __float_as_int(w.x));
    g_epack[p1] = make_int2(s.y, __float_as_int(w.y));
    g_epack[p2] = make_int2(s.z, __float_as_int(w.z));
    g_epack[p3] = make_int2(s.w, __float_as_int(w.w));
}

__global__ void scatter_tail_kernel(const int* __restrict__ src,
                                    const int* __restrict__ dst,
                                    const float* __restrict__ w,
                                    int start, int E) {
    int e = start + blockIdx.x * blockDim.x + threadIdx.x;
    if (e >= E) return;
    int pos = atomicAdd(&g_cursor[dst[e]], 1);
    g_epack[pos] = make_int2(src[e], __float_as_int(w[e]));
}

// Warp-per-node CSR aggregate with grid-stride node loop (balances Poisson
// degree spread over ~4 nodes/warp); fp32 gathers, X emitted in fp16.
__global__ void __launch_bounds__(256)
agg_csr_kernel(const float4* __restrict__ h, uint2* __restrict__ Xf, int n) {
    int gw    = (blockIdx.x * blockDim.x + threadIdx.x) >> 5;
    int nwarp = (gridDim.x * blockDim.x) >> 5;
    int lane  = threadIdx.x & 31;
    const unsigned FULL = 0xffffffffu;
    int l8 = lane & 7;

    for (int node = gw; node < n; node += nwarp) {
        int start = g_off[node];
        int end   = g_off[node + 1];
        float4 acc = make_float4(0.f, 0.f, 0.f, 0.f);
        int idx0 = start + l8;
        int2 p = (idx0 < end) ? g_epack[idx0] : make_int2(0, 0);
        for (int base = start; base < end; base += 8) {
            int2 cur = p;
            int nidx = base + 8 + l8;
            p = (nidx < end) ? g_epack[nidx] : make_int2(0, 0);

            int   ss[8];
            float ww[8];
#pragma unroll
            for (int j = 0; j < 8; j++) {
                ss[j] = __shfl_sync(FULL, cur.x, j);
                ww[j] = __int_as_float(__shfl_sync(FULL, cur.y, j));
            }
            float4 v[8];
#pragma unroll
            for (int j = 0; j < 8; j++)
                v[j] = (base + j < end) ? h[ss[j] * 32 + lane]
                                        : make_float4(0.f, 0.f, 0.f, 0.f);
#pragma unroll
            for (int j = 0; j < 8; j++) {
                acc.x = fmaf(v[j].x, ww[j], acc.x);
                acc.y = fmaf(v[j].y, ww[j], acc.y);
                acc.z = fmaf(v[j].z, ww[j], acc.z);
                acc.w = fmaf(v[j].w, ww[j], acc.w);
            }
        }
        float sm = g_scales[node];
        float sh = g_scales[n + node];
        float4 self = h[node * 32 + lane];
        float ox = fmaf(sm, acc.x, sh * self.x);
        float oy = fmaf(sm, acc.y, sh * self.y);
        float oz = fmaf(sm, acc.z, sh * self.z);
        float ow = fmaf(sm, acc.w, sh * self.w);
        __half2 p01 = __floats2half2_rn(ox, oy);
        __half2 p23 = __floats2half2_rn(oz, ow);
        uint2 u;
        u.x = *reinterpret_cast<uint32_t*>(&p01);
        u.y = *reinterpret_cast<uint32_t*>(&p23);
        Xf[node * 32 + lane] = u;
    }
}

// ---------------------------------------------------------------------------
// fp16 tensor-core update (R11-proven): hout = relu(X @ W^T + b).
__device__ __forceinline__ void mma_f16(float acc[4], const uint32_t a[4],
                                        uint32_t b0, uint32_t b1) {
    asm volatile(
        "mma.sync.aligned.m16n8k16.row.col.f32.f16.f16.f32 "
        "{%0,%1,%2,%3}, {%4,%5,%6,%7}, {%8,%9}, {%0,%1,%2,%3};"
        : "+f"(acc[0]), "+f"(acc[1]), "+f"(acc[2]), "+f"(acc[3])
        : "r"(a[0]), "r"(a[1]), "r"(a[2]), "r"(a[3]), "r"(b0), "r"(b1));
}

__global__ void __launch_bounds__(256)
update_kernel(const uint2* __restrict__ X,   // [N][32] half2-pairs
              const float* __restrict__ W,   // [128,128] row-major [o][k]
              const float* __restrict__ bias,
              float* __restrict__ hout, int n) {
    extern __shared__ uint32_t smw[];
    uint32_t* Whi = smw;                       // 64 * 136
    uint32_t* Wlo = smw + 64 * WPITCH16;       // 64 * 136
    uint32_t* Xs  = smw + 2 * 64 * WPITCH16;   // 64 * 68
    int tid = threadIdx.x;

    for (int i = tid; i < 64 * 128; i += 256) {
        int o = i >> 6, kp = i & 63;
        float2 w2 = reinterpret_cast<const float2*>(W)[o * 64 + kp];
        __half hx = __float2half_rn(w2.x);
        __half hy = __float2half_rn(w2.y);
        __half lx = __float2half_rn(w2.x - __half2float(hx));
        __half ly = __float2half_rn(w2.y - __half2float(hy));
        __half2 hh = __halves2half2(hx, hy);
        __half2 ll = __halves2half2(lx, ly);
        Whi[kp * WPITCH16 + o] = *reinterpret_cast<uint32_t*>(&hh);
        Wlo[kp * WPITCH16 + o] = *reinterpret_cast<uint32_t*>(&ll);
    }

    int lane = tid & 31, warp = tid >> 5;
    int grp = lane >> 2, tig = lane & 3;
    int wm = warp >> 2, wn = warp & 3;
    int rm = wm * 32 + grp;
    int cw = wn * 32 + grp;

    int ntiles = (n + 63) >> 6;
    for (int tile = blockIdx.x; tile < ntiles; tile += gridDim.x) {
        __syncthreads();
        int n0 = tile << 6;
        for (int i = tid; i < 64 * 32; i += 256) {
            int row = i >> 5, l = i & 31;
            uint2 v = make_uint2(0u, 0u);
            if (n0 + row < n) v = X[(n0 + row) * 32 + l];
            *reinterpret_cast<uint2*>(&Xs[row * XPITCH + l * 2]) = v;
        }
        __syncthreads();

        float acc[2][4][4];
#pragma unroll
        for (int nb = 0; nb < 4; nb++) {
            int c = wn * 32 + nb * 8 + 2 * tig;
            float b0 = bias[c], b1 = bias[c + 1];
#pragma unroll
            for (int mb = 0; mb < 2; mb++) {
                acc[mb][nb][0] = b0; acc[mb][nb][1] = b1;
                acc[mb][nb][2] = b0; acc[mb][nb][3] = b1;
            }
        }

#pragma unroll
        for (int k0 = 0; k0 < 128; k0 += 16) {
            int p0 = (k0 >> 1) + tig;
            uint32_t a[2][4];
#pragma unroll
            for (int mb = 0; mb < 2; mb++) {
                int r0 = rm + mb * 16;
                a[mb][0] = Xs[r0 * XPITCH + p0];
                a[mb][1] = Xs[(r0 + 8) * XPITCH + p0];
                a[mb][2] = Xs[r0 * XPITCH + p0 + 4];
                a[mb][3] = Xs[(r0 + 8) * XPITCH + p0 + 4];
            }
#pragma unroll
            for (int pass = 0; pass < 2; pass++) {
                uint32_t* Wp = pass ? Wlo : Whi;
#pragma unroll
                for (int nb = 0; nb < 4; nb++) {
                    uint32_t b0 = Wp[p0 * WPITCH16 + cw + nb * 8];
                    uint32_t b1 = Wp[(p0 + 4) * WPITCH16 + cw + nb * 8];
#pragma unroll
                    for (int mb = 0; mb < 2; mb++)
                        mma_f16(acc[mb][nb], a[mb], b0, b1);
                }
            }
        }

#pragma unroll
        for (int mb = 0; mb < 2; mb++) {
            int r0 = n0 + wm * 32 + mb * 16 + grp;
            int r1 = r0 + 8;
#pragma unroll
            for (int nb = 0; nb < 4; nb++) {
                int c = wn * 32 + nb * 8 + 2 * tig;
                if (r0 < n) {
                    float2 v0 = make_float2(fmaxf(acc[mb][nb][0], 0.f),
                                            fmaxf(acc[mb][nb][1], 0.f));
                    *reinterpret_cast<float2*>(&hout[r0 * FDIM + c]) = v0;
                }
                if (r1 < n) {
                    float2 v1 = make_float2(fmaxf(acc[mb][nb][2], 0.f),
                                            fmaxf(acc[mb][nb][3], 0.f));
                    *reinterpret_cast<float2*>(&hout[r1 * FDIM + c]) = v1;
                }
            }
        }
    }
}

// Final classifier: out = h2 @ Wo^T + bo  (exact grid, one node per warp)
__global__ void __launch_bounds__(256)
out_kernel(const float4* __restrict__ h2,
           const float* __restrict__ Wo, const float* __restrict__ bo,
           float* __restrict__ out, int n) {
    __shared__ float Wos[FDIM * 32];
    int tid = threadIdx.x;
    for (int i = tid; i < 32 * FDIM; i += 256) {
        int o = i >> 7, k = i & 127;
        Wos[k * 32 + o] = Wo[i];
    }
    __syncthreads();

    int lane = tid & 31;
    int wp   = tid >> 5;
    int node = blockIdx.x * 8 + wp;
    if (node >= n) return;
    float acc = bo[lane];
    float4 x = h2[node * 32 + lane];
#pragma unroll
    for (int j = 0; j < 32; j++) {
        float a = __shfl_sync(0xffffffffu, x.x, j);
        float b = __shfl_sync(0xffffffffu, x.y, j);
        float c = __shfl_sync(0xffffffffu, x.z, j);
        float d = __shfl_sync(0xffffffffu, x.w, j);
        int k = j << 2;
        acc += a * Wos[(k + 0) * 32 + lane];
        acc += b * Wos[(k + 1) * 32 + lane];
        acc += c * Wos[(k + 2) * 32 + lane];
        acc += d * Wos[(k + 3) * 32 + lane];
    }
    out[node * 32 + lane] = acc;
}

// ---------------------------------------------------------------------------
extern "C" void kernel_launch(void* const* d_in, const int* in_sizes, int n_in,
                              void* d_out, int out_size) {
    const float* features = (const float*)d_in[0];
    const int*   src      = (const int*)  d_in[1];
    const int*   dst      = (const int*)  d_in[2];
    const float* weight   = (const float*)d_in[3];
    const float* W1       = (const float*)d_in[4];
    const float* b1       = (const float*)d_in[5];
    const float* W2       = (const float*)d_in[6];
    const float* b2       = (const float*)d_in[7];
    const float* Wo       = (const float*)d_in[8];
    const float* bo       = (const float*)d_in[9];
    float* out = (float*)d_out;

    int N = in_sizes[0] / FDIM;
    int E = in_sizes[1];

    void *pXf_v, *ph1_v, *ph2_v, *ppack_v;
    cudaGetSymbolAddress(&pXf_v, g_Xf);
    cudaGetSymbolAddress(&ph1_v, g_h1);
    cudaGetSymbolAddress(&ph2_v, g_h2);
    cudaGetSymbolAddress(&ppack_v, g_pack);
    uint2* pXf = (uint2*)pXf_v;
    float* ph1 = (float*)ph1_v;
    float* ph2 = (float*)ph2_v;

    const int smem_bytes = (2 * 64 * WPITCH16 + 64 * XPITCH) * 4;  // 87040
    cudaFuncSetAttribute(update_kernel,
                         cudaFuncAttributeMaxDynamicSharedMemorySize, smem_bytes);

    int nb = (N + SCAN_BLK - 1) / SCAN_BLK;
    int Eq = E >> 2;          // quads
    int Et = Eq << 2;         // handled by quad kernels

    // CSR build (shared by both layers)
    cudaMemsetAsync(ppack_v, 0, N * sizeof(unsigned long long));
    edge_stats_kernel<<<(Eq + 255) / 256, 256>>>(
        (const int4*)dst, (const float4*)weight, Eq);
    if (Et < E)
        edge_stats_tail_kernel<<<1, 256>>>(dst, weight, Et, E);
    scan_partial_kernel<<<nb, SCAN_BLK>>>(N);
    scan_top_kernel<<<1, MAX_PART>>>(nb, N);
    scan_emit_kernel<<<nb, SCAN_BLK>>>(N);
    scatter_kernel<<<(Eq + 255) / 256, 256>>>(
        (const int4*)src, (const int4*)dst, (const float4*)weight, Eq);
    if (Et < E)
        scatter_tail_kernel<<<1, 256>>>(src, dst, weight, Et, E);

    int agg_grid = 1184;   // 8 blocks/SM, grid-stride warps (~4 nodes/warp)
    int upd_grid = 296;    // 2 blocks/SM

    // Layer 1
    agg_csr_kernel<<<agg_grid, 256>>>((const float4*)features, pXf, N);
    update_kernel<<<upd_grid, 256, smem_bytes>>>(pXf, W1, b1, ph1, N);

    // Layer 2
    agg_csr_kernel<<<agg_grid, 256>>>((const float4*)ph1, pXf, N);
    update_kernel<<<upd_grid, 256, smem_bytes>>>(pXf, W2, b2, ph2, N);

    // Classifier
    out_kernel<<<(N + 7) / 8, 256>>>((const float4*)ph2, Wo, bo, out, N);
}

// round 13
// speedup vs baseline: 1.7711x; 1.7711x over previous
#include <cuda_runtime.h>
#include <cuda_fp16.h>
#include <cstdint>

#define MAXN 40000
#define MAXE 1048576
#define FDIM 128
#define SCAN_BLK 1024
#define MAX_PART 64
#define XPITCH 68     // words, X tile pitch (bank-distinct A frags)
#define WPITCH16 136  // words, W tile pitch (bank-distinct B frags)

// Static scratch (no allocation allowed)
__device__ unsigned long long g_pack[MAXN];  // deg<<40 | sumw*2^20
__device__ float g_scales [2 * MAXN];        // [0,N): sm   [N,2N): sh
__device__ int   g_off    [MAXN + 1];
__device__ int   g_cursor [MAXN];
__device__ int   g_part   [MAX_PART];
__device__ int   g_partoff[MAX_PART];
__device__ int2  g_epack  [MAXE];            // .x = src, .y = float bits of w
__device__ uint2 g_Xf [MAXN * (FDIM / 4)];   // X in fp16 (half2 pairs)
__device__ float g_h1 [MAXN * FDIM];

// ---------------------------------------------------------------------------
__global__ void edge_stats_kernel(const int* __restrict__ dst,
                                  const float* __restrict__ w, int E) {
    int e = blockIdx.x * blockDim.x + threadIdx.x;
    if (e >= E) return;
    unsigned long long add =
        (1ULL << 40) | (unsigned long long)__float2uint_rn(w[e] * 1048576.f);
    atomicAdd(&g_pack[dst[e]], add);
}

__global__ void __launch_bounds__(SCAN_BLK)
scan_partial_kernel(int n) {
    __shared__ int sh[SCAN_BLK];
    int tid = threadIdx.x;
    int i = blockIdx.x * SCAN_BLK + tid;
    sh[tid] = (i < n) ? (int)(g_pack[i] >> 40) : 0;
    __syncthreads();
    for (int d = SCAN_BLK / 2; d > 0; d >>= 1) {
        if (tid < d) sh[tid] += sh[tid + d];
        __syncthreads();
    }
    if (tid == 0) g_part[blockIdx.x] = sh[0];
}

__global__ void scan_top_kernel(int nb, int n) {
    __shared__ int sh[MAX_PART];
    int tid = threadIdx.x;
    int v = (tid < nb) ? g_part[tid] : 0;
    sh[tid] = v;
    __syncthreads();
    for (int d = 1; d < MAX_PART; d <<= 1) {
        int t = (tid >= d) ? sh[tid - d] : 0;
        __syncthreads();
        sh[tid] += t;
        __syncthreads();
    }
    if (tid < nb) g_partoff[tid] = sh[tid] - v;
    if (tid == 0) g_off[n] = sh[nb - 1];
}

__global__ void __launch_bounds__(SCAN_BLK)
scan_emit_kernel(int n) {
    __shared__ int sh[SCAN_BLK];
    int tid = threadIdx.x;
    int i = blockIdx.x * SCAN_BLK + tid;
    unsigned long long pk = (i < n) ? g_pack[i] : 0ULL;
    int dg = (int)(pk >> 40);
    sh[tid] = dg;
    __syncthreads();
    for (int d = 1; d < SCAN_BLK; d <<= 1) {
        int t = (tid >= d) ? sh[tid - d] : 0;
        __syncthreads();
        sh[tid] += t;
        __syncthreads();
    }
    if (i < n) {
        int ex = sh[tid] - dg + g_partoff[blockIdx.x];
        g_off[i]    = ex;
        g_cursor[i] = ex;
        float sw = (float)(pk & ((1ULL << 40) - 1ULL)) * (1.0f / 1048576.f);
        float dgf = (float)dg;
        float smv = 0.f, shv = 0.f;
        if (dg > 0) {
            float inv = 1.0f / (dgf + 1.0f);
            shv = inv;
            float swp = (sw == 0.f) ? 1.f : sw;
            smv = dgf * inv / swp;
        }
        g_scales[i]     = smv;
        g_scales[n + i] = shv;
    }
}

__global__ void scatter_kernel(const int* __restrict__ src,
                               const int* __restrict__ dst,
                               const float* __restrict__ w, int E) {
    int e = blockIdx.x * blockDim.x + threadIdx.x;
    if (e >= E) return;
    int d = dst[e];
    int pos = atomicAdd(&g_cursor[d], 1);
    g_epack[pos] = make_int2(src[e], __float_as_int(w[e]));
}

// Warp-per-node CSR aggregate (R11-proven exact grid); X emitted in fp16.
__global__ void __launch_bounds__(256)
agg_csr_kernel(const float4* __restrict__ h, uint2* __restrict__ Xf, int n) {
    int node = (blockIdx.x * blockDim.x + threadIdx.x) >> 5;
    int lane = threadIdx.x & 31;
    if (node >= n) return;
    int start = g_off[node];
    int end   = g_off[node + 1];
    float4 acc = make_float4(0.f, 0.f, 0.f, 0.f);
    const unsigned FULL = 0xffffffffu;
    int l8 = lane & 7;
    int idx0 = start + l8;
    int2 p = (idx0 < end) ? g_epack[idx0] : make_int2(0, 0);
    for (int base = start; base < end; base += 8) {
        int2 cur = p;
        int nidx = base + 8 + l8;
        p = (nidx < end) ? g_epack[nidx] : make_int2(0, 0);

        int   ss[8];
        float ww[8];
#pragma unroll
        for (int j = 0; j < 8; j++) {
            ss[j] = __shfl_sync(FULL, cur.x, j);
            ww[j] = __int_as_float(__shfl_sync(FULL, cur.y, j));
        }
        float4 v[8];
#pragma unroll
        for (int j = 0; j < 8; j++)
            v[j] = (base + j < end) ? h[ss[j] * 32 + lane]
                                    : make_float4(0.f, 0.f, 0.f, 0.f);
#pragma unroll
        for (int j = 0; j < 8; j++) {
            acc.x = fmaf(v[j].x, ww[j], acc.x);
            acc.y = fmaf(v[j].y, ww[j], acc.y);
            acc.z = fmaf(v[j].z, ww[j], acc.z);
            acc.w = fmaf(v[j].w, ww[j], acc.w);
        }
    }
    float sm = g_scales[node];
    float sh = g_scales[n + node];
    float4 self = h[node * 32 + lane];
    float ox = fmaf(sm, acc.x, sh * self.x);
    float oy = fmaf(sm, acc.y, sh * self.y);
    float oz = fmaf(sm, acc.z, sh * self.z);
    float ow = fmaf(sm, acc.w, sh * self.w);
    __half2 p01 = __floats2half2_rn(ox, oy);
    __half2 p23 = __floats2half2_rn(oz, ow);
    uint2 u;
    u.x = *reinterpret_cast<uint32_t*>(&p01);
    u.y = *reinterpret_cast<uint32_t*>(&p23);
    Xf[node * 32 + lane] = u;
}

// ---------------------------------------------------------------------------
// fp16 tensor-core update (R11-proven): h' = relu(X @ W^T + b).
// Fold mode (out2 != nullptr): instead of writing h' to gmem, stage the relu'd
// tile in smem (fp16) and apply the classifier: out = h' @ Wo^T + bo.
__device__ __forceinline__ void mma_f16(float acc[4], const uint32_t a[4],
                                        uint32_t b0, uint32_t b1) {
    asm volatile(
        "mma.sync.aligned.m16n8k16.row.col.f32.f16.f16.f32 "
        "{%0,%1,%2,%3}, {%4,%5,%6,%7}, {%8,%9}, {%0,%1,%2,%3};"
        : "+f"(acc[0]), "+f"(acc[1]), "+f"(acc[2]), "+f"(acc[3])
        : "r"(a[0]), "r"(a[1]), "r"(a[2]), "r"(a[3]), "r"(b0), "r"(b1));
}

__global__ void __launch_bounds__(256)
update_kernel(const uint2* __restrict__ X,   // [N][32] half2-pairs
              const float* __restrict__ W,   // [128,128] row-major [o][k]
              const float* __restrict__ bias,
              float* __restrict__ hout,      // used when out2 == nullptr
              const float* __restrict__ Wo,  // [32,128] or nullptr
              const float* __restrict__ bo,  // [32]     or nullptr
              float* __restrict__ out2,      // [N,32]   or nullptr
              int n) {
    extern __shared__ uint32_t smw[];
    uint32_t* Whi = smw;                        // 64 * 136
    uint32_t* Wlo = smw + 64 * WPITCH16;        // 64 * 136
    uint32_t* Xs  = smw + 2 * 64 * WPITCH16;    // 64 * 68 (X tile / h2 stage)
    float*    Wos = reinterpret_cast<float*>(Xs + 64 * XPITCH);  // 128*32
    int tid = threadIdx.x;

    for (int i = tid; i < 64 * 128; i += 256) {
        int o = i >> 6, kp = i & 63;
        float2 w2 = reinterpret_cast<const float2*>(W)[o * 64 + kp];
        __half hx = __float2half_rn(w2.x);
        __half hy = __float2half_rn(w2.y);
        __half lx = __float2half_rn(w2.x - __half2float(hx));
        __half ly = __float2half_rn(w2.y - __half2float(hy));
        __half2 hh = __halves2half2(hx, hy);
        __half2 ll = __halves2half2(lx, ly);
        Whi[kp * WPITCH16 + o] = *reinterpret_cast<uint32_t*>(&hh);
        Wlo[kp * WPITCH16 + o] = *reinterpret_cast<uint32_t*>(&ll);
    }
    if (out2) {
        // Wos[k][o] = Wo[o][k]
        for (int i = tid; i < 32 * 128; i += 256) {
            int o = i >> 7, k = i & 127;
            Wos[k * 32 + o] = Wo[i];
        }
    }

    int lane = tid & 31, warp = tid >> 5;
    int grp = lane >> 2, tig = lane & 3;
    int wm = warp >> 2, wn = warp & 3;
    int rm = wm * 32 + grp;
    int cw = wn * 32 + grp;
    float bo_l = out2 ? bo[lane] : 0.f;

    int ntiles = (n + 63) >> 6;
    for (int tile = blockIdx.x; tile < ntiles; tile += gridDim.x) {
        __syncthreads();
        int n0 = tile << 6;
        for (int i = tid; i < 64 * 32; i += 256) {
            int row = i >> 5, l = i & 31;
            uint2 v = make_uint2(0u, 0u);
            if (n0 + row < n) v = X[(n0 + row) * 32 + l];
            *reinterpret_cast<uint2*>(&Xs[row * XPITCH + l * 2]) = v;
        }
        __syncthreads();

        float acc[2][4][4];
#pragma unroll
        for (int nb = 0; nb < 4; nb++) {
            int c = wn * 32 + nb * 8 + 2 * tig;
            float b0 = bias[c], b1 = bias[c + 1];
#pragma unroll
            for (int mb = 0; mb < 2; mb++) {
                acc[mb][nb][0] = b0; acc[mb][nb][1] = b1;
                acc[mb][nb][2] = b0; acc[mb][nb][3] = b1;
            }
        }

#pragma unroll
        for (int k0 = 0; k0 < 128; k0 += 16) {
            int p0 = (k0 >> 1) + tig;
            uint32_t a[2][4];
#pragma unroll
            for (int mb = 0; mb < 2; mb++) {
                int r0 = rm + mb * 16;
                a[mb][0] = Xs[r0 * XPITCH + p0];
                a[mb][1] = Xs[(r0 + 8) * XPITCH + p0];
                a[mb][2] = Xs[r0 * XPITCH + p0 + 4];
                a[mb][3] = Xs[(r0 + 8) * XPITCH + p0 + 4];
            }
#pragma unroll
            for (int pass = 0; pass < 2; pass++) {
                uint32_t* Wp = pass ? Wlo : Whi;
#pragma unroll
                for (int nb = 0; nb < 4; nb++) {
                    uint32_t b0 = Wp[p0 * WPITCH16 + cw + nb * 8];
                    uint32_t b1 = Wp[(p0 + 4) * WPITCH16 + cw + nb * 8];
#pragma unroll
                    for (int mb = 0; mb < 2; mb++)
                        mma_f16(acc[mb][nb], a[mb], b0, b1);
                }
            }
        }

        if (!out2) {
            // Normal epilogue: relu + fp32 store
#pragma unroll
            for (int mb = 0; mb < 2; mb++) {
                int r0 = n0 + wm * 32 + mb * 16 + grp;
                int r1 = r0 + 8;
#pragma unroll
                for (int nb = 0; nb < 4; nb++) {
                    int c = wn * 32 + nb * 8 + 2 * tig;
                    if (r0 < n) {
                        float2 v0 = make_float2(fmaxf(acc[mb][nb][0], 0.f),
                                                fmaxf(acc[mb][nb][1], 0.f));
                        *reinterpret_cast<float2*>(&hout[r0 * FDIM + c]) = v0;
                    }
                    if (r1 < n) {
                        float2 v1 = make_float2(fmaxf(acc[mb][nb][2], 0.f),
                                                fmaxf(acc[mb][nb][3], 0.f));
                        *reinterpret_cast<float2*>(&hout[r1 * FDIM + c]) = v1;
                    }
                }
            }
        } else {
            // Fold epilogue: relu -> stage h2 tile as fp16 in Xs -> classifier
            __syncthreads();   // all warps done reading Xs in mainloop
#pragma unroll
            for (int mb = 0; mb < 2; mb++) {
                int rl0 = wm * 32 + mb * 16 + grp;
#pragma unroll
                for (int nb = 0; nb < 4; nb++) {
                    int cp = wn * 16 + nb * 4 + tig;   // half2-pair column
                    __half2 h0 = __floats2half2_rn(fmaxf(acc[mb][nb][0], 0.f),
                                                   fmaxf(acc[mb][nb][1], 0.f));
                    __half2 h1 = __floats2half2_rn(fmaxf(acc[mb][nb][2], 0.f),
                                                   fmaxf(acc[mb][nb][3], 0.f));
                    Xs[rl0 * XPITCH + cp]       = *reinterpret_cast<uint32_t*>(&h0);
                    Xs[(rl0 + 8) * XPITCH + cp] = *reinterpret_cast<uint32_t*>(&h1);
                }
            }
            __syncthreads();

            // Warp `warp` handles rows [8*warp, 8*warp+8); lane = out channel
            float acc2[8];
#pragma unroll
            for (int r = 0; r < 8; r++) acc2[r] = bo_l;
#pragma unroll 8
            for (int kp = 0; kp < 64; kp++) {
                float w0 = Wos[(2 * kp) * 32 + lane];
                float w1 = Wos[(2 * kp + 1) * 32 + lane];
#pragma unroll
                for (int r = 0; r < 8; r++) {
                    uint32_t u = Xs[(warp * 8 + r) * XPITCH + kp];
                    float2 f = __half22float2(*reinterpret_cast<const __half2*>(&u));
                    acc2[r] = fmaf(f.x, w0, acc2[r]);
                    acc2[r] = fmaf(f.y, w1, acc2[r]);
                }
            }
#pragma unroll
            for (int r = 0; r < 8; r++) {
                int node = n0 + warp * 8 + r;
                if (node < n) out2[node * 32 + lane] = acc2[r];
            }
        }
    }
}

// ---------------------------------------------------------------------------
extern "C" void kernel_launch(void* const* d_in, const int* in_sizes, int n_in,
                              void* d_out, int out_size) {
    const float* features = (const float*)d_in[0];
    const int*   src      = (const int*)  d_in[1];
    const int*   dst      = (const int*)  d_in[2];
    const float* weight   = (const float*)d_in[3];
    const float* W1       = (const float*)d_in[4];
    const float* b1       = (const float*)d_in[5];
    const float* W2       = (const float*)d_in[6];
    const float* b2       = (const float*)d_in[7];
    const float* Wo       = (const float*)d_in[8];
    const float* bo       = (const float*)d_in[9];
    float* out = (float*)d_out;

    int N = in_sizes[0] / FDIM;
    int E = in_sizes[1];

    void *pXf_v, *ph1_v, *ppack_v;
    cudaGetSymbolAddress(&pXf_v, g_Xf);
    cudaGetSymbolAddress(&ph1_v, g_h1);
    cudaGetSymbolAddress(&ppack_v, g_pack);
    uint2* pXf = (uint2*)pXf_v;
    float* ph1 = (float*)ph1_v;

    const int smem_bytes =
        (2 * 64 * WPITCH16 + 64 * XPITCH + 128 * 32) * 4;  // 103424
    cudaFuncSetAttribute(update_kernel,
                         cudaFuncAttributeMaxDynamicSharedMemorySize, smem_bytes);

    int nb = (N + SCAN_BLK - 1) / SCAN_BLK;

    // CSR build (shared by both layers)
    cudaMemsetAsync(ppack_v, 0, N * sizeof(unsigned long long));
    edge_stats_kernel<<<(E + 255) / 256, 256>>>(dst, weight, E);
    scan_partial_kernel<<<nb, SCAN_BLK>>>(N);
    scan_top_kernel<<<1, MAX_PART>>>(nb, N);
    scan_emit_kernel<<<nb, SCAN_BLK>>>(N);
    scatter_kernel<<<(E + 255) / 256, 256>>>(src, dst, weight, E);

    int agg_grid = (N * 32 + 255) / 256;
    int upd_grid = 296;   // 2 blocks/SM

    // Layer 1
    agg_csr_kernel<<<agg_grid, 256>>>((const float4*)features, pXf, N);
    update_kernel<<<upd_grid, 256, smem_bytes>>>(
        pXf, W1, b1, ph1, nullptr, nullptr, nullptr, N);

    // Layer 2 + fused classifier
    agg_csr_kernel<<<agg_grid, 256>>>((const float4*)ph1, pXf, N);
    update_kernel<<<upd_grid, 256, smem_bytes>>>(
        pXf, W2, b2, nullptr, Wo, bo, out, N);
}

// round 14
// speedup vs baseline: 1.8036x; 1.0183x over previous
#include <cuda_runtime.h>
#include <cuda_fp16.h>
#include <cstdint>

#define MAXN 40000
#define MAXE 1048576
#define FDIM 128
#define SCAN_BLK 1024
#define MAX_PART 64
#define XPITCH 68     // words, X tile pitch (bank-distinct A frags)
#define WPITCH16 136  // words, W tile pitch (bank-distinct B frags)

// Static scratch (no allocation allowed)
__device__ unsigned long long g_pack[MAXN];  // deg<<40 | sumw*2^20
__device__ float g_scales [2 * MAXN];        // [0,N): sm   [N,2N): sh
__device__ int   g_off    [MAXN + 1];
__device__ int   g_cursor [MAXN];
__device__ int   g_part   [MAX_PART];
__device__ int   g_partoff[MAX_PART];
__device__ int2  g_epack  [MAXE];            // .x = src, .y = float bits of w
__device__ uint2 g_Xf [MAXN * (FDIM / 4)];   // X in fp16 (half2 pairs)
__device__ uint2 g_h16[MAXN * (FDIM / 4)];   // h gather table, fp16

// ---------------------------------------------------------------------------
// 4 edges per thread, int4/float4 streams, 4 independent atomics (MLP=4)
__global__ void edge_stats4_kernel(const int4* __restrict__ dst4,
                                   const float4* __restrict__ w4, int nq) {
    int i = blockIdx.x * blockDim.x + threadIdx.x;
    if (i >= nq) return;
    int4 d = dst4[i];
    float4 w = w4[i];
    atomicAdd(&g_pack[d.x], (1ULL << 40) | (unsigned long long)__float2uint_rn(w.x * 1048576.f));
    atomicAdd(&g_pack[d.y], (1ULL << 40) | (unsigned long long)__float2uint_rn(w.y * 1048576.f));
    atomicAdd(&g_pack[d.z], (1ULL << 40) | (unsigned long long)__float2uint_rn(w.z * 1048576.f));
    atomicAdd(&g_pack[d.w], (1ULL << 40) | (unsigned long long)__float2uint_rn(w.w * 1048576.f));
}

__global__ void edge_stats_tail_kernel(const int* __restrict__ dst,
                                       const float* __restrict__ w,
                                       int start, int E) {
    int e = start + blockIdx.x * blockDim.x + threadIdx.x;
    if (e >= E) return;
    atomicAdd(&g_pack[dst[e]],
              (1ULL << 40) | (unsigned long long)__float2uint_rn(w[e] * 1048576.f));
}

__global__ void __launch_bounds__(SCAN_BLK)
scan_partial_kernel(int n) {
    __shared__ int sh[SCAN_BLK];
    int tid = threadIdx.x;
    int i = blockIdx.x * SCAN_BLK + tid;
    sh[tid] = (i < n) ? (int)(g_pack[i] >> 40) : 0;
    __syncthreads();
    for (int d = SCAN_BLK / 2; d > 0; d >>= 1) {
        if (tid < d) sh[tid] += sh[tid + d];
        __syncthreads();
    }
    if (tid == 0) g_part[blockIdx.x] = sh[0];
}

__global__ void scan_top_kernel(int nb, int n) {
    __shared__ int sh[MAX_PART];
    int tid = threadIdx.x;
    int v = (tid < nb) ? g_part[tid] : 0;
    sh[tid] = v;
    __syncthreads();
    for (int d = 1; d < MAX_PART; d <<= 1) {
        int t = (tid >= d) ? sh[tid - d] : 0;
        __syncthreads();
        sh[tid] += t;
        __syncthreads();
    }
    if (tid < nb) g_partoff[tid] = sh[tid] - v;
    if (tid == 0) g_off[n] = sh[nb - 1];
}

__global__ void __launch_bounds__(SCAN_BLK)
scan_emit_kernel(int n) {
    __shared__ int sh[SCAN_BLK];
    int tid = threadIdx.x;
    int i = blockIdx.x * SCAN_BLK + tid;
    unsigned long long pk = (i < n) ? g_pack[i] : 0ULL;
    int dg = (int)(pk >> 40);
    sh[tid] = dg;
    __syncthreads();
    for (int d = 1; d < SCAN_BLK; d <<= 1) {
        int t = (tid >= d) ? sh[tid - d] : 0;
        __syncthreads();
        sh[tid] += t;
        __syncthreads();
    }
    if (i < n) {
        int ex = sh[tid] - dg + g_partoff[blockIdx.x];
        g_off[i]    = ex;
        g_cursor[i] = ex;
        float sw = (float)(pk & ((1ULL << 40) - 1ULL)) * (1.0f / 1048576.f);
        float dgf = (float)dg;
        float smv = 0.f, shv = 0.f;
        if (dg > 0) {
            float inv = 1.0f / (dgf + 1.0f);
            shv = inv;
            float swp = (sw == 0.f) ? 1.f : sw;
            smv = dgf * inv / swp;
        }
        g_scales[i]     = smv;
        g_scales[n + i] = shv;
    }
}

// 4 edges per thread (MLP=4 on cursor atomics)
__global__ void scatter4_kernel(const int4* __restrict__ src4,
                                const int4* __restrict__ dst4,
                                const float4* __restrict__ w4, int nq) {
    int i = blockIdx.x * blockDim.x + threadIdx.x;
    if (i >= nq) return;
    int4 s = src4[i];
    int4 d = dst4[i];
    float4 w = w4[i];
    int p0 = atomicAdd(&g_cursor[d.x], 1);
    int p1 = atomicAdd(&g_cursor[d.y], 1);
    int p2 = atomicAdd(&g_cursor[d.z], 1);
    int p3 = atomicAdd(&g_cursor[d.w], 1);
    g_epack[p0] = make_int2(s.x, __float_as_int(w.x));
    g_epack[p1] = make_int2(s.y, __float_as_int(w.y));
    g_epack[p2] = make_int2(s.z, __float_as_int(w.z));
    g_epack[p3] = make_int2(s.w, __float_as_int(w.w));
}

__global__ void scatter_tail_kernel(const int* __restrict__ src,
                                    const int* __restrict__ dst,
                                    const float* __restrict__ w,
                                    int start, int E) {
    int e = start + blockIdx.x * blockDim.x + threadIdx.x;
    if (e >= E) return;
    int pos = atomicAdd(&g_cursor[dst[e]], 1);
    g_epack[pos] = make_int2(src[e], __float_as_int(w[e]));
}

// fp32 features -> fp16 gather table (once)
__global__ void convert_f16_kernel(const float4* __restrict__ h, int n4) {
    int i = blockIdx.x * blockDim.x + threadIdx.x;
    if (i >= n4) return;
    float4 v = h[i];
    __half2 p0 = __floats2half2_rn(v.x, v.y);
    __half2 p1 = __floats2half2_rn(v.z, v.w);
    uint2 u;
    u.x = *reinterpret_cast<uint32_t*>(&p0);
    u.y = *reinterpret_cast<uint32_t*>(&p1);
    g_h16[i] = u;
}

// Warp-per-node CSR aggregate (exact grid). Gathers + self from the fp16
// table (256B/warp, halved L2 traffic); weights & accumulation fp32.
__global__ void __launch_bounds__(256)
agg_csr_kernel(uint2* __restrict__ Xf, int n) {
    int node = (blockIdx.x * blockDim.x + threadIdx.x) >> 5;
    int lane = threadIdx.x & 31;
    if (node >= n) return;
    int start = g_off[node];
    int end   = g_off[node + 1];
    float4 acc = make_float4(0.f, 0.f, 0.f, 0.f);
    const unsigned FULL = 0xffffffffu;
    int l8 = lane & 7;
    int idx0 = start + l8;
    int2 p = (idx0 < end) ? g_epack[idx0] : make_int2(0, 0);
    for (int base = start; base < end; base += 8) {
        int2 cur = p;
        int nidx = base + 8 + l8;
        p = (nidx < end) ? g_epack[nidx] : make_int2(0, 0);

        int   ss[8];
        float ww[8];
#pragma unroll
        for (int j = 0; j < 8; j++) {
            ss[j] = __shfl_sync(FULL, cur.x, j);
            ww[j] = __int_as_float(__shfl_sync(FULL, cur.y, j));
        }
        uint2 v[8];
#pragma unroll
        for (int j = 0; j < 8; j++)
            v[j] = (base + j < end) ? g_h16[ss[j] * 32 + lane]
                                    : make_uint2(0u, 0u);
#pragma unroll
        for (int j = 0; j < 8; j++) {
            float2 f01 = __half22float2(*reinterpret_cast<const __half2*>(&v[j].x));
            float2 f23 = __half22float2(*reinterpret_cast<const __half2*>(&v[j].y));
            acc.x = fmaf(f01.x, ww[j], acc.x);
            acc.y = fmaf(f01.y, ww[j], acc.y);
            acc.z = fmaf(f23.x, ww[j], acc.z);
            acc.w = fmaf(f23.y, ww[j], acc.w);
        }
    }
    float sm = g_scales[node];
    float sh = g_scales[n + node];
    uint2 su = g_h16[node * 32 + lane];
    float2 s01 = __half22float2(*reinterpret_cast<const __half2*>(&su.x));
    float2 s23 = __half22float2(*reinterpret_cast<const __half2*>(&su.y));
    float ox = fmaf(sm, acc.x, sh * s01.x);
    float oy = fmaf(sm, acc.y, sh * s01.y);
    float oz = fmaf(sm, acc.z, sh * s23.x);
    float ow = fmaf(sm, acc.w, sh * s23.y);
    __half2 p01 = __floats2half2_rn(ox, oy);
    __half2 p23 = __floats2half2_rn(oz, ow);
    uint2 u;
    u.x = *reinterpret_cast<uint32_t*>(&p01);
    u.y = *reinterpret_cast<uint32_t*>(&p23);
    Xf[node * 32 + lane] = u;
}

// ---------------------------------------------------------------------------
// fp16 tensor-core update (R11/R13-proven): h' = relu(X @ W^T + b).
// Layer-1 mode (hout16):  write h' as fp16 into the gather table.
// Fold mode   (out2):     stage relu'd tile in smem, apply classifier.
__device__ __forceinline__ void mma_f16(float acc[4], const uint32_t a[4],
                                        uint32_t b0, uint32_t b1) {
    asm volatile(
        "mma.sync.aligned.m16n8k16.row.col.f32.f16.f16.f32 "
        "{%0,%1,%2,%3}, {%4,%5,%6,%7}, {%8,%9}, {%0,%1,%2,%3};"
        : "+f"(acc[0]), "+f"(acc[1]), "+f"(acc[2]), "+f"(acc[3])
        : "r"(a[0]), "r"(a[1]), "r"(a[2]), "r"(a[3]), "r"(b0), "r"(b1));
}

__global__ void __launch_bounds__(256)
update_kernel(const uint2* __restrict__ X,       // [N][32] half2-pairs
              const float* __restrict__ W,       // [128,128] row-major [o][k]
              const float* __restrict__ bias,
              uint32_t* __restrict__ hout16,     // fp16 h table (layer 1) or null
              const float* __restrict__ Wo,      // [32,128] or null
              const float* __restrict__ bo,      // [32]     or null
              float* __restrict__ out2,          // [N,32]   or null
              int n) {
    extern __shared__ uint32_t smw[];
    uint32_t* Whi = smw;                        // 64 * 136
    uint32_t* Wlo = smw + 64 * WPITCH16;        // 64 * 136
    uint32_t* Xs  = smw + 2 * 64 * WPITCH16;    // 64 * 68 (X tile / h2 stage)
    float*    Wos = reinterpret_cast<float*>(Xs + 64 * XPITCH);  // 128*32
    int tid = threadIdx.x;

    for (int i = tid; i < 64 * 128; i += 256) {
        int o = i >> 6, kp = i & 63;
        float2 w2 = reinterpret_cast<const float2*>(W)[o * 64 + kp];
        __half hx = __float2half_rn(w2.x);
        __half hy = __float2half_rn(w2.y);
        __half lx = __float2half_rn(w2.x - __half2float(hx));
        __half ly = __float2half_rn(w2.y - __half2float(hy));
        __half2 hh = __halves2half2(hx, hy);
        __half2 ll = __halves2half2(lx, ly);
        Whi[kp * WPITCH16 + o] = *reinterpret_cast<uint32_t*>(&hh);
        Wlo[kp * WPITCH16 + o] = *reinterpret_cast<uint32_t*>(&ll);
    }
    if (out2) {
        for (int i = tid; i < 32 * 128; i += 256) {
            int o = i >> 7, k = i & 127;
            Wos[k * 32 + o] = Wo[i];
        }
    }

    int lane = tid & 31, warp = tid >> 5;
    int grp = lane >> 2, tig = lane & 3;
    int wm = warp >> 2, wn = warp & 3;
    int rm = wm * 32 + grp;
    int cw = wn * 32 + grp;
    float bo_l = out2 ? bo[lane] : 0.f;

    int ntiles = (n + 63) >> 6;
    for (int tile = blockIdx.x; tile < ntiles; tile += gridDim.x) {
        __syncthreads();
        int n0 = tile << 6;
        for (int i = tid; i < 64 * 32; i += 256) {
            int row = i >> 5, l = i & 31;
            uint2 v = make_uint2(0u, 0u);
            if (n0 + row < n) v = X[(n0 + row) * 32 + l];
            *reinterpret_cast<uint2*>(&Xs[row * XPITCH + l * 2]) = v;
        }
        __syncthreads();

        float acc[2][4][4];
#pragma unroll
        for (int nb = 0; nb < 4; nb++) {
            int c = wn * 32 + nb * 8 + 2 * tig;
            float b0 = bias[c], b1 = bias[c + 1];
#pragma unroll
            for (int mb = 0; mb < 2; mb++) {
                acc[mb][nb][0] = b0; acc[mb][nb][1] = b1;
                acc[mb][nb][2] = b0; acc[mb][nb][3] = b1;
            }
        }

#pragma unroll
        for (int k0 = 0; k0 < 128; k0 += 16) {
            int p0 = (k0 >> 1) + tig;
            uint32_t a[2][4];
#pragma unroll
            for (int mb = 0; mb < 2; mb++) {
                int r0 = rm + mb * 16;
                a[mb][0] = Xs[r0 * XPITCH + p0];
                a[mb][1] = Xs[(r0 + 8) * XPITCH + p0];
                a[mb][2] = Xs[r0 * XPITCH + p0 + 4];
                a[mb][3] = Xs[(r0 + 8) * XPITCH + p0 + 4];
            }
#pragma unroll
            for (int pass = 0; pass < 2; pass++) {
                uint32_t* Wp = pass ? Wlo : Whi;
#pragma unroll
                for (int nb = 0; nb < 4; nb++) {
                    uint32_t b0 = Wp[p0 * WPITCH16 + cw + nb * 8];
                    uint32_t b1 = Wp[(p0 + 4) * WPITCH16 + cw + nb * 8];
#pragma unroll
                    for (int mb = 0; mb < 2; mb++)
                        mma_f16(acc[mb][nb], a[mb], b0, b1);
                }
            }
        }

        if (!out2) {
            // Layer-1 epilogue: relu + fp16 store into the gather table
#pragma unroll
            for (int mb = 0; mb < 2; mb++) {
                int r0 = n0 + wm * 32 + mb * 16 + grp;
                int r1 = r0 + 8;
#pragma unroll
                for (int nb = 0; nb < 4; nb++) {
                    int cp = wn * 16 + nb * 4 + tig;   // half2-pair column
                    if (r0 < n) {
                        __half2 h0 = __floats2half2_rn(fmaxf(acc[mb][nb][0], 0.f),
                                                       fmaxf(acc[mb][nb][1], 0.f));
                        hout16[r0 * 64 + cp] = *reinterpret_cast<uint32_t*>(&h0);
                    }
                    if (r1 < n) {
                        __half2 h1 = __floats2half2_rn(fmaxf(acc[mb][nb][2], 0.f),
                                                       fmaxf(acc[mb][nb][3], 0.f));
                        hout16[r1 * 64 + cp] = *reinterpret_cast<uint32_t*>(&h1);
                    }
                }
            }
        } else {
            // Fold epilogue: relu -> stage h2 tile as fp16 in Xs -> classifier
            __syncthreads();
#pragma unroll
            for (int mb = 0; mb < 2; mb++) {
                int rl0 = wm * 32 + mb * 16 + grp;
#pragma unroll
                for (int nb = 0; nb < 4; nb++) {
                    int cp = wn * 16 + nb * 4 + tig;
                    __half2 h0 = __floats2half2_rn(fmaxf(acc[mb][nb][0], 0.f),
                                                   fmaxf(acc[mb][nb][1], 0.f));
                    __half2 h1 = __floats2half2_rn(fmaxf(acc[mb][nb][2], 0.f),
                                                   fmaxf(acc[mb][nb][3], 0.f));
                    Xs[rl0 * XPITCH + cp]       = *reinterpret_cast<uint32_t*>(&h0);
                    Xs[(rl0 + 8) * XPITCH + cp] = *reinterpret_cast<uint32_t*>(&h1);
                }
            }
            __syncthreads();

            float acc2[8];
#pragma unroll
            for (int r = 0; r < 8; r++) acc2[r] = bo_l;
#pragma unroll 8
            for (int kp = 0; kp < 64; kp++) {
                float w0 = Wos[(2 * kp) * 32 + lane];
                float w1 = Wos[(2 * kp + 1) * 32 + lane];
#pragma unroll
                for (int r = 0; r < 8; r++) {
                    uint32_t u = Xs[(warp * 8 + r) * XPITCH + kp];
                    float2 f = __half22float2(*reinterpret_cast<const __half2*>(&u));
                    acc2[r] = fmaf(f.x, w0, acc2[r]);
                    acc2[r] = fmaf(f.y, w1, acc2[r]);
                }
            }
#pragma unroll
            for (int r = 0; r < 8; r++) {
                int node = n0 + warp * 8 + r;
                if (node < n) out2[node * 32 + lane] = acc2[r];
            }
        }
    }
}

// ---------------------------------------------------------------------------
extern "C" void kernel_launch(void* const* d_in, const int* in_sizes, int n_in,
                              void* d_out, int out_size) {
    const float* features = (const float*)d_in[0];
    const int*   src      = (const int*)  d_in[1];
    const int*   dst      = (const int*)  d_in[2];
    const float* weight   = (const float*)d_in[3];
    const float* W1       = (const float*)d_in[4];
    const float* b1       = (const float*)d_in[5];
    const float* W2       = (const float*)d_in[6];
    const float* b2       = (const float*)d_in[7];
    const float* Wo       = (const float*)d_in[8];
    const float* bo       = (const float*)d_in[9];
    float* out = (float*)d_out;

    int N = in_sizes[0] / FDIM;
    int E = in_sizes[1];

    void *pXf_v, *ph16_v, *ppack_v;
    cudaGetSymbolAddress(&pXf_v, g_Xf);
    cudaGetSymbolAddress(&ph16_v, g_h16);
    cudaGetSymbolAddress(&ppack_v, g_pack);
    uint2* pXf = (uint2*)pXf_v;
    uint32_t* ph16 = (uint32_t*)ph16_v;

    const int smem_bytes =
        (2 * 64 * WPITCH16 + 64 * XPITCH + 128 * 32) * 4;  // 103424
    cudaFuncSetAttribute(update_kernel,
                         cudaFuncAttributeMaxDynamicSharedMemorySize, smem_bytes);

    int nb = (N + SCAN_BLK - 1) / SCAN_BLK;
    int Eq = E >> 2;
    int Et = Eq << 2;

    // CSR build (shared by both layers) + feature fp16 table
    cudaMemsetAsync(ppack_v, 0, N * sizeof(unsigned long long));
    edge_stats4_kernel<<<(Eq + 255) / 256, 256>>>(
        (const int4*)dst, (const float4*)weight, Eq);
    if (Et < E) edge_stats_tail_kernel<<<1, 256>>>(dst, weight, Et, E);
    scan_partial_kernel<<<nb, SCAN_BLK>>>(N);
    scan_top_kernel<<<1, MAX_PART>>>(nb, N);
    scan_emit_kernel<<<nb, SCAN_BLK>>>(N);
    scatter4_kernel<<<(Eq + 255) / 256, 256>>>(
        (const int4*)src, (const int4*)dst, (const float4*)weight, Eq);
    if (Et < E) scatter_tail_kernel<<<1, 256>>>(src, dst, weight, Et, E);
    convert_f16_kernel<<<(N * 32 + 255) / 256, 256>>>((const float4*)features, N * 32);

    int agg_grid = (N * 32 + 255) / 256;
    int upd_grid = 296;   // 2 blocks/SM

    // Layer 1 (h1 written fp16-only into the gather table)
    agg_csr_kernel<<<agg_grid, 256>>>(pXf, N);
    update_kernel<<<upd_grid, 256, smem_bytes>>>(
        pXf, W1, b1, ph16, nullptr, nullptr, nullptr, N);

    // Layer 2 + fused classifier
    agg_csr_kernel<<<agg_grid, 256>>>(pXf, N);
    update_kernel<<<upd_grid, 256, smem_bytes>>>(
        pXf, W2, b2, nullptr, Wo, bo, out, N);
}